// round 1
// baseline (speedup 1.0000x reference)
#include <cuda_runtime.h>
#include <math.h>

// Problem constants
#define B_   4
#define L_   1024
#define DIM_ 1024
#define H_   8
#define D_   32

// Scratch (static device allocations are allowed; cudaMalloc is not)
__device__ float g_u   [(size_t)4096 * 1024];  // silu(x @ W_in^T + b_in)
__device__ float g_qkva[(size_t)4096 * 2048];  // u @ W_qkva^T + b_qkva
__device__ float g_y2  [(size_t)4096 * 512];   // scan output (pre W_y)
__device__ float g_z   [(size_t)4096 * 1024];  // silu(y2 @ W_y^T + b_y)

// ---------------------------------------------------------------------------
// SGEMM (TN): C[m,n] = act( sum_k A[m,k] * B[n,k] + bias[n] )
// A: [M,K] row-major, B: [N,K] row-major (weight layout), both K-contiguous.
// Tile 128x128x8, 256 threads, 8x8 per-thread microtile, double-buffered smem.
// Requires M%128==0, N%128==0, K%8==0 (true for all four calls).
// ---------------------------------------------------------------------------
template <bool SILU>
__global__ void __launch_bounds__(256, 2) sgemm_tn(
    const float* __restrict__ A, const float* __restrict__ Bm,
    const float* __restrict__ bias, float* __restrict__ C,
    int M, int N, int K)
{
    __shared__ __align__(16) float As[2][8][132];
    __shared__ __align__(16) float Bs[2][8][132];

    const int tid = threadIdx.x;
    const int m0  = blockIdx.y * 128;
    const int n0  = blockIdx.x * 128;

    // global-load assignment: 128 rows x 2 float4 (8 k) per operand
    const int lrow = tid >> 1;
    const int lk4  = (tid & 1) * 4;
    const float* Ag = A  + (size_t)(m0 + lrow) * K + lk4;
    const float* Bg = Bm + (size_t)(n0 + lrow) * K + lk4;

    float4 ra = *(const float4*)Ag;
    float4 rb = *(const float4*)Bg;

    const int tm0 = (tid >> 4) * 8;   // 16 row-groups
    const int tn0 = (tid & 15) * 8;   // 16 col-groups

    float acc[8][8];
#pragma unroll
    for (int i = 0; i < 8; ++i)
#pragma unroll
        for (int j = 0; j < 8; ++j) acc[i][j] = 0.0f;

    const int nk = K >> 3;
    int buf = 0;
    for (int kt = 0; kt < nk; ++kt) {
        // stage current k-tile (transposed: [k][row])
        As[buf][lk4 + 0][lrow] = ra.x;
        As[buf][lk4 + 1][lrow] = ra.y;
        As[buf][lk4 + 2][lrow] = ra.z;
        As[buf][lk4 + 3][lrow] = ra.w;
        Bs[buf][lk4 + 0][lrow] = rb.x;
        Bs[buf][lk4 + 1][lrow] = rb.y;
        Bs[buf][lk4 + 2][lrow] = rb.z;
        Bs[buf][lk4 + 3][lrow] = rb.w;
        __syncthreads();

        if (kt + 1 < nk) {  // prefetch next tile while computing
            ra = *(const float4*)(Ag + (size_t)(kt + 1) * 8);
            rb = *(const float4*)(Bg + (size_t)(kt + 1) * 8);
        }

#pragma unroll
        for (int k = 0; k < 8; ++k) {
            float af[8], bf[8];
            *(float4*)(af)     = *(const float4*)(&As[buf][k][tm0]);
            *(float4*)(af + 4) = *(const float4*)(&As[buf][k][tm0 + 4]);
            *(float4*)(bf)     = *(const float4*)(&Bs[buf][k][tn0]);
            *(float4*)(bf + 4) = *(const float4*)(&Bs[buf][k][tn0 + 4]);
#pragma unroll
            for (int i = 0; i < 8; ++i)
#pragma unroll
                for (int j = 0; j < 8; ++j)
                    acc[i][j] += af[i] * bf[j];
        }
        buf ^= 1;
    }

    // epilogue: bias + optional silu, vectorized stores
    float bv[8];
#pragma unroll
    for (int j = 0; j < 8; ++j) bv[j] = bias[n0 + tn0 + j];

#pragma unroll
    for (int i = 0; i < 8; ++i) {
        float v[8];
#pragma unroll
        for (int j = 0; j < 8; ++j) {
            float c = acc[i][j] + bv[j];
            if (SILU) c = c / (1.0f + __expf(-c));
            v[j] = c;
        }
        float* cr = C + (size_t)(m0 + tm0 + i) * N + (n0 + tn0);
        *(float4*)(cr)     = *(float4*)(v);
        *(float4*)(cr + 4) = *(float4*)(v + 4);
    }
}

// ---------------------------------------------------------------------------
// Scan kernel.
// qkva: [b, l, h, d, 4, 2] float  (per (b,l,h,d): q_re,q_im,k_re,k_im,v_re,v_im,a_re,a_im)
// Block = (e-group, h, b): 4 x 8 x 4 = 128 blocks, 256 threads.
// warp (0..7) owns column e = eg*8 + warp; lane owns row d.
// State h[d,e] complex kept in registers; recurrence:
//   h = a[d]*h + k[d]*v[e];  y[l,e] = sum_d q[d]*h[d,e]
// Gate: a *= sqrt(m)/(1+m), m=|a|^2  (== rsqrt(m)*sigmoid(log m)).
// Initial state folded in by initializing h = h0[h,d,e] (step 0 then applies
// h = a0*h0 + k0 v0, matching the reference's kv[:,0] += a0*h0).
// ---------------------------------------------------------------------------
__global__ void __launch_bounds__(256) scan_kernel(
    const float* __restrict__ qkva,
    const float* __restrict__ h0re, const float* __restrict__ h0im,
    float* __restrict__ y2)
{
    __shared__ float2 sq[2][8][32];
    __shared__ float2 sk[2][8][32];
    __shared__ float2 sv[2][8][32];
    __shared__ float2 sa[2][8][32];

    const int eg   = blockIdx.x;  // 0..3
    const int h    = blockIdx.y;  // 0..7
    const int b    = blockIdx.z;  // 0..3
    const int tid  = threadIdx.x;
    const int warp = tid >> 5;
    const int lane = tid & 31;
    const int ecol = eg * 8 + warp;

    // register state: h0[h, d=lane, e=ecol]
    float hre = h0re[(h * 32 + lane) * 32 + ecol];
    float him = h0im[(h * 32 + lane) * 32 + ecol];

    // base in float4: per (b,l,h) group of 256 floats = 64 float4; per-l stride = 512 float4
    const float4* gq = (const float4*)qkva + ((size_t)(b * L_) * H_ + h) * 64;

    const int id0 = tid;        // loads 512 float4 per 8-step chunk, 2 per thread
    const int id1 = tid + 256;
    const int r0w = id0 >> 6, f0 = id0 & 63;  // row-in-chunk, float4-within-row
    const int r1w = id1 >> 6, f1 = id1 & 63;
    const int d0 = f0 >> 1, half0 = f0 & 1;
    const int d1 = f1 >> 1, half1 = f1 & 1;

    // prefetch chunk 0
    float4 va = gq[(size_t)r0w * 512 + f0];
    float4 vb = gq[(size_t)r1w * 512 + f1];

    int p = 0;
    for (int c = 0; c < 128; ++c) {
        // de-interleave into SoA smem + gate a in-register
        if (half0 == 0) {
            sq[p][r0w][d0] = make_float2(va.x, va.y);
            sk[p][r0w][d0] = make_float2(va.z, va.w);
        } else {
            sv[p][r0w][d0] = make_float2(va.x, va.y);
            float m = va.z * va.z + va.w * va.w;
            float s = sqrtf(m) / (1.0f + m);
            sa[p][r0w][d0] = make_float2(va.z * s, va.w * s);
        }
        if (half1 == 0) {
            sq[p][r1w][d1] = make_float2(vb.x, vb.y);
            sk[p][r1w][d1] = make_float2(vb.z, vb.w);
        } else {
            sv[p][r1w][d1] = make_float2(vb.x, vb.y);
            float m = vb.z * vb.z + vb.w * vb.w;
            float s = sqrtf(m) / (1.0f + m);
            sa[p][r1w][d1] = make_float2(vb.z * s, vb.w * s);
        }
        __syncthreads();

        if (c + 1 < 128) {  // prefetch next chunk (hides L2/DRAM latency behind 8 steps)
            size_t off = (size_t)(c + 1) * 8 * 512;
            va = gq[off + (size_t)r0w * 512 + f0];
            vb = gq[off + (size_t)r1w * 512 + f1];
        }

#pragma unroll
        for (int s = 0; s < 8; ++s) {
            float2 aa = sa[p][s][lane];
            float2 kk = sk[p][s][lane];
            float2 qq = sq[p][s][lane];
            float2 vv = sv[p][s][ecol];  // broadcast

            float nr = aa.x * hre - aa.y * him + (kk.x * vv.x - kk.y * vv.y);
            float ni = aa.x * him + aa.y * hre + (kk.x * vv.y + kk.y * vv.x);
            hre = nr;
            him = ni;

            float tr = qq.x * hre - qq.y * him;
            float ti = qq.x * him + qq.y * hre;
#pragma unroll
            for (int off = 16; off > 0; off >>= 1) {
                tr += __shfl_xor_sync(0xffffffffu, tr, off);
                ti += __shfl_xor_sync(0xffffffffu, ti, off);
            }
            if (lane == 0) {
                int l = c * 8 + s;
                ((float2*)y2)[(size_t)(b * L_ + l) * 256 + h * 32 + ecol] =
                    make_float2(tr, ti);
            }
        }
        p ^= 1;
    }
}

// ---------------------------------------------------------------------------
// Launch: 5 kernels, all graph-capturable, no allocations.
// Input order: x, W_in, b_in, W_qkva, b_qkva, W_y, b_y, W_out, b_out, h0_re, h0_im
// ---------------------------------------------------------------------------
extern "C" void kernel_launch(void* const* d_in, const int* in_sizes, int n_in,
                              void* d_out, int out_size)
{
    const float* x      = (const float*)d_in[0];
    const float* W_in   = (const float*)d_in[1];
    const float* b_in   = (const float*)d_in[2];
    const float* W_qkva = (const float*)d_in[3];
    const float* b_qkva = (const float*)d_in[4];
    const float* W_y    = (const float*)d_in[5];
    const float* b_y    = (const float*)d_in[6];
    const float* W_out  = (const float*)d_in[7];
    const float* b_out  = (const float*)d_in[8];
    const float* h0re   = (const float*)d_in[9];
    const float* h0im   = (const float*)d_in[10];

    float *u, *qkva, *y2, *z;
    cudaGetSymbolAddress((void**)&u,    g_u);
    cudaGetSymbolAddress((void**)&qkva, g_qkva);
    cudaGetSymbolAddress((void**)&y2,   g_y2);
    cudaGetSymbolAddress((void**)&z,    g_z);

    dim3 thr(256);
    // u = silu(x @ W_in^T + b_in)          [4096,1024] x [1024,1024]
    sgemm_tn<true ><<<dim3(1024 / 128, 4096 / 128), thr>>>(x,  W_in,   b_in,   u,    4096, 1024, 1024);
    // qkva = u @ W_qkva^T + b_qkva         [4096,1024] x [2048,1024]^T
    sgemm_tn<false><<<dim3(2048 / 128, 4096 / 128), thr>>>(u,  W_qkva, b_qkva, qkva, 4096, 2048, 1024);
    // scan -> y2                           [4096, 512]
    scan_kernel<<<dim3(4, H_, B_), thr>>>(qkva, h0re, h0im, y2);
    // z = silu(y2 @ W_y^T + b_y)           [4096,512] x [1024,512]^T
    sgemm_tn<true ><<<dim3(1024 / 128, 4096 / 128), thr>>>(y2, W_y,    b_y,    z,    4096, 1024, 512);
    // out = z @ W_out^T + b_out            [4096,1024] x [1024,1024]^T
    sgemm_tn<false><<<dim3(1024 / 128, 4096 / 128), thr>>>(z,  W_out,  b_out,  (float*)d_out, 4096, 1024, 1024);
}

// round 3
// speedup vs baseline: 2.2931x; 2.2931x over previous
#include <cuda_runtime.h>
#include <cuda_bf16.h>
#include <math.h>
#include <stdint.h>

#define B_   4
#define L_   1024
#define H_   8

// ---------------------------------------------------------------------------
// Scratch buffers. Split-precision pairs stored as [2][rows][K]: plane0=hi.
// ---------------------------------------------------------------------------
__device__ __align__(256) __nv_bfloat16 g_xs [(size_t)2 * 4096 * 1024];
__device__ __align__(256) __nv_bfloat16 g_w1s[(size_t)2 * 1024 * 1024];
__device__ __align__(256) __nv_bfloat16 g_w2s[(size_t)2 * 2048 * 1024];
__device__ __align__(256) __nv_bfloat16 g_w3s[(size_t)2 * 1024 * 512];
__device__ __align__(256) __nv_bfloat16 g_w4s[(size_t)2 * 1024 * 1024];
__device__ __align__(256) __nv_bfloat16 g_us [(size_t)2 * 4096 * 1024];
__device__ __align__(256) float         g_qkva[(size_t)4096 * 2048];
__device__ __align__(256) __nv_bfloat16 g_y2s[(size_t)2 * 4096 * 512];
__device__ __align__(256) __nv_bfloat16 g_zs [(size_t)2 * 4096 * 1024];

// ---------------------------------------------------------------------------
// PTX helpers (sm_80-class only: cp.async, ldmatrix, mma.sync)
// ---------------------------------------------------------------------------
__device__ __forceinline__ uint32_t smem_u32(const void* p) {
    uint32_t a;
    asm("{ .reg .u64 t; cvta.to.shared.u64 t, %1; cvt.u32.u64 %0, t; }"
        : "=r"(a) : "l"(p));
    return a;
}

#define CPA16(dst, src) \
    asm volatile("cp.async.cg.shared.global [%0], [%1], 16;" :: "r"(dst), "l"(src))
#define CPA_COMMIT() asm volatile("cp.async.commit_group;" ::: "memory")
#define CPA_WAIT0()  asm volatile("cp.async.wait_group 0;" ::: "memory")
#define CPA_WAIT1()  asm volatile("cp.async.wait_group 1;" ::: "memory")

#define LDSM_X4(r0, r1, r2, r3, addr)                                        \
    asm volatile("ldmatrix.sync.aligned.m8n8.x4.shared.b16 {%0,%1,%2,%3}, [%4];" \
        : "=r"(r0), "=r"(r1), "=r"(r2), "=r"(r3) : "r"(addr))

#define MMA16816(d, a, b)                                                    \
    asm volatile("mma.sync.aligned.m16n8k16.row.col.f32.bf16.bf16.f32 "      \
        "{%0,%1,%2,%3}, {%4,%5,%6,%7}, {%8,%9}, {%0,%1,%2,%3};"              \
        : "+f"((d)[0]), "+f"((d)[1]), "+f"((d)[2]), "+f"((d)[3])             \
        : "r"((a)[0]), "r"((a)[1]), "r"((a)[2]), "r"((a)[3]),                \
          "r"((b)[0]), "r"((b)[1]))

// SW128 swizzle on a byte offset within a [rows][128B] tile:
// off ^ ((off>>3)&0x70) — only row bits feed the XOR mask.
__device__ __forceinline__ uint32_t sw128(uint32_t off) {
    return off ^ ((off >> 3) & 0x70);
}

// ---------------------------------------------------------------------------
// Split fp32 -> bf16 (hi, lo) planes
// ---------------------------------------------------------------------------
__global__ void split_kernel(const float4* __restrict__ in,
                             __nv_bfloat16* __restrict__ hi,
                             __nv_bfloat16* __restrict__ lo, int n4)
{
    int i = blockIdx.x * blockDim.x + threadIdx.x;
    if (i >= n4) return;
    float4 v = in[i];
    __nv_bfloat162 h0, h1, l0, l1;
    h0.x = __float2bfloat16(v.x); l0.x = __float2bfloat16(v.x - __bfloat162float(h0.x));
    h0.y = __float2bfloat16(v.y); l0.y = __float2bfloat16(v.y - __bfloat162float(h0.y));
    h1.x = __float2bfloat16(v.z); l1.x = __float2bfloat16(v.z - __bfloat162float(h1.x));
    h1.y = __float2bfloat16(v.w); l1.y = __float2bfloat16(v.w - __bfloat162float(h1.y));
    ((__nv_bfloat162*)hi)[2 * i]     = h0;
    ((__nv_bfloat162*)hi)[2 * i + 1] = h1;
    ((__nv_bfloat162*)lo)[2 * i]     = l0;
    ((__nv_bfloat162*)lo)[2 * i + 1] = l1;
}

// ---------------------------------------------------------------------------
// Split-bf16 GEMM via mma.sync:  C[m,n] = act( sum_k A[m,k]*B[n,k] + bias[n] )
// A,B as bf16 (hi,lo) planes, [2][rows][K] row-major, K contiguous.
// CTA 128x128, 256 threads = 8 warps (2x4), warp tile 64x32.
// K-chunk 64, SW128-swizzled smem, 3-stage cp.async pipeline.
// Per k16: 16 mma per warp per product plane; products hi*hi + hi*lo + lo*hi.
// ---------------------------------------------------------------------------
#define STAGE_BYT 65536            // Ahi|Alo|Bhi|Blo each 16KB (128 x 128B)
#define SMEM_TOT  (3 * STAGE_BYT + 1024)

template <bool SILU, bool PAIR>
__global__ void __launch_bounds__(256) mm_kernel(
    const __nv_bfloat16* __restrict__ A, const __nv_bfloat16* __restrict__ Bw,
    const float* __restrict__ bias,
    float* __restrict__ Cf,
    __nv_bfloat16* __restrict__ Ch, __nv_bfloat16* __restrict__ Cl,
    int M, int N, int K)
{
    extern __shared__ char smem_raw[];
    const uint32_t stage0 = (smem_u32(smem_raw) + 1023u) & ~1023u;

    const int tid  = threadIdx.x;
    const int lane = tid & 31;
    const int wid  = tid >> 5;
    const int wm   = wid >> 2;        // 0..1 : 64-row slab
    const int wn   = wid & 3;         // 0..3 : 32-col slab
    const int n0   = blockIdx.x * 128;
    const int m0   = blockIdx.y * 128;

    // ---- global->smem staging (4 tiles x 1024 x 16B per stage) ----
    const int cc = tid & 7;           // 16B chunk within 128B row
    const int rb = tid >> 3;          // row base 0..31
    const __nv_bfloat16* srcs[4] = {
        A  + (size_t)m0 * K,                        // Ahi
        A  + (size_t)M * K + (size_t)m0 * K,        // Alo
        Bw + (size_t)n0 * K,                        // Bhi
        Bw + (size_t)N * K + (size_t)n0 * K         // Blo
    };

    auto load_chunk = [&](int kc, int s) {
        const uint32_t st = stage0 + s * STAGE_BYT;
        const int kbase = kc * 64;
#pragma unroll
        for (int t = 0; t < 4; ++t) {
            const __nv_bfloat16* srcb = srcs[t] + kbase + cc * 8;
#pragma unroll
            for (int jj = 0; jj < 4; ++jj) {
                const int r = rb + jj * 32;
                CPA16(st + t * 16384 + sw128((uint32_t)(r * 128 + cc * 16)),
                      srcb + (size_t)r * K);
            }
        }
        CPA_COMMIT();
    };

    // ---- per-lane ldmatrix address components ----
    // A (m16k16, x4): lanes 0-15 -> rows (lane&15), k-half (lane>>4)
    uint32_t a_row[4], a_msk[4];
#pragma unroll
    for (int im = 0; im < 4; ++im) {
        const int r = wm * 64 + im * 16 + (lane & 15);
        a_row[im] = (uint32_t)(r * 128);
        a_msk[im] = (uint32_t)((r & 7) << 4);
    }
    const uint32_t a_half = (uint32_t)((lane >> 4) << 4);

    // B (two n8k16 tiles per x4): group g = lane>>3:
    //   n = wn*32 + jp*16 + (g>>1)*8 + (lane&7), k-half = (g&1)
    uint32_t b_row[2], b_msk[2];
    {
        const int g = lane >> 3;
#pragma unroll
        for (int jp = 0; jp < 2; ++jp) {
            const int n = wn * 32 + jp * 16 + ((g >> 1) << 3) + (lane & 7);
            b_row[jp] = (uint32_t)(n * 128);
            b_msk[jp] = (uint32_t)((n & 7) << 4);
        }
    }
    const uint32_t b_half = (uint32_t)((lane & 8) << 1);   // (g&1)*16

    float acc[4][4][4];
#pragma unroll
    for (int i = 0; i < 4; ++i)
#pragma unroll
        for (int j = 0; j < 4; ++j)
#pragma unroll
            for (int q = 0; q < 4; ++q) acc[i][j][q] = 0.0f;

    const int nch = K >> 6;
    load_chunk(0, 0);
    load_chunk(1, 1);

    for (int i = 0; i < nch; ++i) {
        const int s = i % 3;
        if (i + 1 < nch) CPA_WAIT1(); else CPA_WAIT0();
        __syncthreads();
        if (i + 2 < nch) load_chunk(i + 2, (i + 2) % 3);

        const uint32_t ahi = stage0 + s * STAGE_BYT;
        const uint32_t alo = ahi + 16384;
        const uint32_t bhi = ahi + 32768;
        const uint32_t blo = ahi + 49152;

#pragma unroll
        for (int kk = 0; kk < 4; ++kk) {
            const uint32_t kb = (uint32_t)(kk * 32);
            uint32_t ah[4][4], al[4][4], bh[4][2], bl[4][2];
#pragma unroll
            for (int im = 0; im < 4; ++im) {
                const uint32_t off = a_row[im] + ((kb + a_half) ^ a_msk[im]);
                LDSM_X4(ah[im][0], ah[im][1], ah[im][2], ah[im][3], ahi + off);
                LDSM_X4(al[im][0], al[im][1], al[im][2], al[im][3], alo + off);
            }
#pragma unroll
            for (int jp = 0; jp < 2; ++jp) {
                const uint32_t off = b_row[jp] + ((kb + b_half) ^ b_msk[jp]);
                LDSM_X4(bh[jp*2][0], bh[jp*2][1], bh[jp*2+1][0], bh[jp*2+1][1], bhi + off);
                LDSM_X4(bl[jp*2][0], bl[jp*2][1], bl[jp*2+1][0], bl[jp*2+1][1], blo + off);
            }
#pragma unroll
            for (int im = 0; im < 4; ++im)
#pragma unroll
                for (int jn = 0; jn < 4; ++jn) {
                    MMA16816(acc[im][jn], ah[im], bh[jn]);
                    MMA16816(acc[im][jn], ah[im], bl[jn]);
                    MMA16816(acc[im][jn], al[im], bh[jn]);
                }
        }
    }

    // ---- epilogue: bias + optional silu; fp32 or bf16 hi/lo pair ----
    const int qr = lane >> 2;         // 0..7
    const int qc = (lane & 3) * 2;
#pragma unroll
    for (int jn = 0; jn < 4; ++jn) {
        const int col = n0 + wn * 32 + jn * 8 + qc;
        const float b0 = bias[col], b1 = bias[col + 1];
#pragma unroll
        for (int im = 0; im < 4; ++im) {
            const int row = m0 + wm * 64 + im * 16 + qr;
            float v[4];
            v[0] = acc[im][jn][0] + b0;
            v[1] = acc[im][jn][1] + b1;
            v[2] = acc[im][jn][2] + b0;
            v[3] = acc[im][jn][3] + b1;
            if (SILU) {
#pragma unroll
                for (int q = 0; q < 4; ++q)
                    v[q] = v[q] * (1.0f / (1.0f + __expf(-v[q])));
            }
            if (!PAIR) {
                *(float2*)(Cf + (size_t)row * N + col)       = make_float2(v[0], v[1]);
                *(float2*)(Cf + (size_t)(row + 8) * N + col) = make_float2(v[2], v[3]);
            } else {
                __nv_bfloat162 hh, ll;
                hh.x = __float2bfloat16(v[0]); hh.y = __float2bfloat16(v[1]);
                ll.x = __float2bfloat16(v[0] - __bfloat162float(hh.x));
                ll.y = __float2bfloat16(v[1] - __bfloat162float(hh.y));
                *(__nv_bfloat162*)(Ch + (size_t)row * N + col) = hh;
                *(__nv_bfloat162*)(Cl + (size_t)row * N + col) = ll;
                hh.x = __float2bfloat16(v[2]); hh.y = __float2bfloat16(v[3]);
                ll.x = __float2bfloat16(v[2] - __bfloat162float(hh.x));
                ll.y = __float2bfloat16(v[3] - __bfloat162float(hh.y));
                *(__nv_bfloat162*)(Ch + (size_t)(row + 8) * N + col) = hh;
                *(__nv_bfloat162*)(Cl + (size_t)(row + 8) * N + col) = ll;
            }
        }
    }
}

// ---------------------------------------------------------------------------
// Scan kernel. qkva: [b,l,h,d,4,2] fp32. Block=(e-group,h,b); warp=e-column,
// lane=d.  h = gate(a[d])*h + k[d]*v[e];  y[l,e] = sum_d q[d]*h[d,e]
// gate: a *= sqrt(m)/(1+m), m=|a|^2 (== rsqrt(m)*sigmoid(log m)).
// Output: bf16 hi/lo planes of y2 [4096][512], col = h*64 + e*2 (+0 re,+1 im).
// ---------------------------------------------------------------------------
__global__ void __launch_bounds__(256) scan_kernel(
    const float* __restrict__ qkva,
    const float* __restrict__ h0re, const float* __restrict__ h0im,
    __nv_bfloat16* __restrict__ y2h, __nv_bfloat16* __restrict__ y2l)
{
    __shared__ float2 sq[2][8][32];
    __shared__ float2 sk[2][8][32];
    __shared__ float2 sv[2][8][32];
    __shared__ float2 sa[2][8][32];

    const int eg   = blockIdx.x;
    const int h    = blockIdx.y;
    const int b    = blockIdx.z;
    const int tid  = threadIdx.x;
    const int warp = tid >> 5;
    const int lane = tid & 31;
    const int ecol = eg * 8 + warp;

    float hre = h0re[(h * 32 + lane) * 32 + ecol];
    float him = h0im[(h * 32 + lane) * 32 + ecol];

    const float4* gq = (const float4*)qkva + ((size_t)(b * L_) * H_ + h) * 64;

    const int id0 = tid, id1 = tid + 256;
    const int r0w = id0 >> 6, f0 = id0 & 63;
    const int r1w = id1 >> 6, f1 = id1 & 63;
    const int d0 = f0 >> 1, half0 = f0 & 1;
    const int d1 = f1 >> 1, half1 = f1 & 1;

    float4 va = gq[(size_t)r0w * 512 + f0];
    float4 vb = gq[(size_t)r1w * 512 + f1];

    int p = 0;
    for (int c = 0; c < 128; ++c) {
        if (half0 == 0) {
            sq[p][r0w][d0] = make_float2(va.x, va.y);
            sk[p][r0w][d0] = make_float2(va.z, va.w);
        } else {
            sv[p][r0w][d0] = make_float2(va.x, va.y);
            float m = va.z * va.z + va.w * va.w;
            float s = sqrtf(m) / (1.0f + m);
            sa[p][r0w][d0] = make_float2(va.z * s, va.w * s);
        }
        if (half1 == 0) {
            sq[p][r1w][d1] = make_float2(vb.x, vb.y);
            sk[p][r1w][d1] = make_float2(vb.z, vb.w);
        } else {
            sv[p][r1w][d1] = make_float2(vb.x, vb.y);
            float m = vb.z * vb.z + vb.w * vb.w;
            float s = sqrtf(m) / (1.0f + m);
            sa[p][r1w][d1] = make_float2(vb.z * s, vb.w * s);
        }
        __syncthreads();

        if (c + 1 < 128) {
            size_t off = (size_t)(c + 1) * 8 * 512;
            va = gq[off + (size_t)r0w * 512 + f0];
            vb = gq[off + (size_t)r1w * 512 + f1];
        }

#pragma unroll
        for (int s = 0; s < 8; ++s) {
            float2 aa = sa[p][s][lane];
            float2 kk = sk[p][s][lane];
            float2 qq = sq[p][s][lane];
            float2 vv = sv[p][s][ecol];

            float nr = aa.x * hre - aa.y * him + (kk.x * vv.x - kk.y * vv.y);
            float ni = aa.x * him + aa.y * hre + (kk.x * vv.y + kk.y * vv.x);
            hre = nr; him = ni;

            float tr = qq.x * hre - qq.y * him;
            float ti = qq.x * him + qq.y * hre;
#pragma unroll
            for (int off = 16; off > 0; off >>= 1) {
                tr += __shfl_xor_sync(0xffffffffu, tr, off);
                ti += __shfl_xor_sync(0xffffffffu, ti, off);
            }
            if (lane == 0) {
                const int l = c * 8 + s;
                const size_t o = (size_t)(b * L_ + l) * 512 + h * 64 + ecol * 2;
                __nv_bfloat162 hh, ll;
                hh.x = __float2bfloat16(tr);
                ll.x = __float2bfloat16(tr - __bfloat162float(hh.x));
                hh.y = __float2bfloat16(ti);
                ll.y = __float2bfloat16(ti - __bfloat162float(hh.y));
                *(__nv_bfloat162*)(y2h + o) = hh;
                *(__nv_bfloat162*)(y2l + o) = ll;
            }
        }
        p ^= 1;
    }
}

// ---------------------------------------------------------------------------
// Launch. Inputs: x, W_in, b_in, W_qkva, b_qkva, W_y, b_y, W_out, b_out,
//                 h0_re, h0_im
// ---------------------------------------------------------------------------
extern "C" void kernel_launch(void* const* d_in, const int* in_sizes, int n_in,
                              void* d_out, int out_size)
{
    const float* x      = (const float*)d_in[0];
    const float* W_in   = (const float*)d_in[1];
    const float* b_in   = (const float*)d_in[2];
    const float* W_qkva = (const float*)d_in[3];
    const float* b_qkva = (const float*)d_in[4];
    const float* W_y    = (const float*)d_in[5];
    const float* b_y    = (const float*)d_in[6];
    const float* W_out  = (const float*)d_in[7];
    const float* b_out  = (const float*)d_in[8];
    const float* h0re   = (const float*)d_in[9];
    const float* h0im   = (const float*)d_in[10];

    __nv_bfloat16 *xs, *w1s, *w2s, *w3s, *w4s, *us, *y2s, *zs;
    float* qkva;
    cudaGetSymbolAddress((void**)&xs,   g_xs);
    cudaGetSymbolAddress((void**)&w1s,  g_w1s);
    cudaGetSymbolAddress((void**)&w2s,  g_w2s);
    cudaGetSymbolAddress((void**)&w3s,  g_w3s);
    cudaGetSymbolAddress((void**)&w4s,  g_w4s);
    cudaGetSymbolAddress((void**)&us,   g_us);
    cudaGetSymbolAddress((void**)&qkva, g_qkva);
    cudaGetSymbolAddress((void**)&y2s,  g_y2s);
    cudaGetSymbolAddress((void**)&zs,   g_zs);

    cudaFuncSetAttribute(mm_kernel<true,  true >,
                         cudaFuncAttributeMaxDynamicSharedMemorySize, SMEM_TOT);
    cudaFuncSetAttribute(mm_kernel<false, false>,
                         cudaFuncAttributeMaxDynamicSharedMemorySize, SMEM_TOT);

    auto split = [&](const float* src, __nv_bfloat16* dst, size_t n) {
        int n4 = (int)(n >> 2);
        split_kernel<<<(n4 + 255) / 256, 256>>>((const float4*)src, dst, dst + n, n4);
    };
    split(x,      xs,  (size_t)4096 * 1024);
    split(W_in,   w1s, (size_t)1024 * 1024);
    split(W_qkva, w2s, (size_t)2048 * 1024);
    split(W_y,    w3s, (size_t)1024 * 512);
    split(W_out,  w4s, (size_t)1024 * 1024);

    // u = silu(x @ W_in^T + b_in)  -> bf16 pair
    mm_kernel<true, true><<<dim3(8, 32), 256, SMEM_TOT>>>(
        xs, w1s, b_in, nullptr, us, us + (size_t)4096 * 1024, 4096, 1024, 1024);
    // qkva = u @ W_qkva^T + b_qkva -> fp32
    mm_kernel<false, false><<<dim3(16, 32), 256, SMEM_TOT>>>(
        us, w2s, b_qkva, qkva, nullptr, nullptr, 4096, 2048, 1024);
    // scan -> y2 bf16 pair
    scan_kernel<<<dim3(4, H_, B_), 256>>>(qkva, h0re, h0im,
                                          y2s, y2s + (size_t)4096 * 512);
    // z = silu(y2 @ W_y^T + b_y) -> bf16 pair
    mm_kernel<true, true><<<dim3(8, 32), 256, SMEM_TOT>>>(
        y2s, w3s, b_y, nullptr, zs, zs + (size_t)4096 * 1024, 4096, 1024, 512);
    // out = z @ W_out^T + b_out -> fp32
    mm_kernel<false, false><<<dim3(8, 32), 256, SMEM_TOT>>>(
        zs, w4s, b_out, (float*)d_out, nullptr, nullptr, 4096, 1024, 1024);
}